// round 15
// baseline (speedup 1.0000x reference)
#include <cuda_runtime.h>
#include <cuda_fp16.h>
#include <cstdint>

#define NN 50000
#define NE 800000

__device__ __align__(16) float g_sums[NN * 64];
__device__ __align__(16) float g_cnt[NN];
__device__ __align__(16) __half g_P[NN * 128];   // P = src @ W1aL^T + b1a (fp16)

__global__ void zero_kernel() {
    int i = blockIdx.x * blockDim.x + threadIdx.x;
    float4 z = make_float4(0.f, 0.f, 0.f, 0.f);
    if (i < NN * 16) ((float4*)g_sums)[i] = z;
    if (i < NN / 4 + 1 && i * 4 + 3 < NN) ((float4*)g_cnt)[i] = z;
    if (i < 4) g_cnt[NN - 1 - i] = 0.f;
}

__device__ __forceinline__ float to_tf32(float x) {
    float y;
    asm("cvt.rna.tf32.f32 %0, %1;" : "=f"(y) : "f"(x));
    return y;
}
__device__ __forceinline__ uint32_t f2h2(float x, float y) {
    __half2 h = __floats2half2_rn(x, y);
    return *reinterpret_cast<uint32_t*>(&h);
}
__device__ __forceinline__ float2 h22f2(uint32_t u) {
    __half2 h = *reinterpret_cast<__half2*>(&u);
    return __half22float2(h);
}

__device__ __forceinline__ void mma_tf32(float d[4], const uint32_t a[4], const uint32_t b[2]) {
    asm volatile(
        "mma.sync.aligned.m16n8k8.row.col.f32.tf32.tf32.f32 "
        "{%0,%1,%2,%3}, {%4,%5,%6,%7}, {%8,%9}, {%0,%1,%2,%3};"
        : "+f"(d[0]), "+f"(d[1]), "+f"(d[2]), "+f"(d[3])
        : "r"(a[0]), "r"(a[1]), "r"(a[2]), "r"(a[3]), "r"(b[0]), "r"(b[1]));
}
__device__ __forceinline__ void mma_f16(float d[4], const uint32_t a[4], const uint32_t b[2]) {
    asm volatile(
        "mma.sync.aligned.m16n8k16.row.col.f32.f16.f16.f32 "
        "{%0,%1,%2,%3}, {%4,%5,%6,%7}, {%8,%9}, {%0,%1,%2,%3};"
        : "+f"(d[0]), "+f"(d[1]), "+f"(d[2]), "+f"(d[3])
        : "r"(a[0]), "r"(a[1]), "r"(a[2]), "r"(a[3]), "r"(b[0]), "r"(b[1]));
}

__device__ __forceinline__ void ldA_s(uint32_t a[4], const char* p, int stride) {
    a[0] = *(const uint32_t*)p;
    a[1] = *(const uint32_t*)(p + 8 * stride);
    a[2] = *(const uint32_t*)(p + 16);
    a[3] = *(const uint32_t*)(p + 8 * stride + 16);
}
__device__ __forceinline__ void ldB(uint32_t b[2], const char* p) {
    b[0] = *(const uint32_t*)p;
    b[1] = *(const uint32_t*)(p + 16);
}

#define REDV2(ptr, x0, x1) \
    asm volatile("red.global.add.v2.f32 [%0], {%1,%2};" :: "l"(ptr), "f"(x0), "f"(x1) : "memory")

__device__ __forceinline__ void cp_async16(void* dst_smem, const void* src_g) {
    uint32_t d;
    asm("{ .reg .u64 t; cvta.to.shared.u64 t, %1; cvt.u32.u64 %0, t; }" : "=r"(d) : "l"(dst_smem));
    asm volatile("cp.async.cg.shared.global [%0], [%1], 16;" :: "r"(d), "l"(src_g) : "memory");
}
#define CP_COMMIT() asm volatile("cp.async.commit_group;" ::: "memory")
#define CP_WAIT0()  asm volatile("cp.async.wait_group 0;" ::: "memory")

#define W68  272     // tf32 rows: 68 floats
#define HB   272     // fp16 rows: 136 halves (conflict-free, proven)

// ============================ P kernel (tf32 compute, fp16 out) ==============
#define PO_A 0
#define PO_W 17408
#define SMEM_P (PO_W + 34816)

__global__ __launch_bounds__(256, 2)
void p_kernel(const float* __restrict__ src, const float* __restrict__ W1a,
              const float* __restrict__ b1a)
{
    extern __shared__ char sm[];
    char* sA = sm + PO_A;
    char* sW = sm + PO_W;
    const int tid = threadIdx.x, lane = tid & 31, w = tid >> 5;
    const int p = w & 1, q = w >> 1;
    const int r4 = lane >> 2, cb = (lane & 3) * 4, c2 = (lane & 3) * 2;

    for (int idx = tid; idx < 128 * 32; idx += 256) {
        int r = idx >> 5, kp2 = idx & 31;
        float2 v = *(const float2*)(W1a + r * 128 + kp2 * 2);
        v.x = to_tf32(v.x); v.y = to_tf32(v.y);
        *(float2*)(sW + r * W68 + kp2 * 8) = v;
    }

    const int base = blockIdx.x * 64;
    for (int idx = tid; idx < 64 * 32; idx += 256) {
        int n = idx >> 5, kp2 = idx & 31;
        int gn = base + n;
        float2 v = make_float2(0.f, 0.f);
        if (gn < NN) v = *(const float2*)(src + (size_t)gn * 64 + kp2 * 2);
        v.x = to_tf32(v.x); v.y = to_tf32(v.y);
        *(float2*)(sA + n * W68 + kp2 * 8) = v;
    }
    __syncthreads();

    float acc[2][4][4];
    #pragma unroll
    for (int s = 0; s < 2; s++)
        #pragma unroll
        for (int j = 0; j < 4; j++)
            { acc[s][j][0]=0.f; acc[s][j][1]=0.f; acc[s][j][2]=0.f; acc[s][j][3]=0.f; }

    #pragma unroll
    for (int k0 = 0; k0 < 8; k0++) {
        int kb = k0 * 32 + cb;
        uint32_t a[2][4];
        ldA_s(a[0], sA + (p * 32 + r4) * W68 + kb, W68);
        ldA_s(a[1], sA + (p * 32 + 16 + r4) * W68 + kb, W68);
        #pragma unroll
        for (int j = 0; j < 4; j++) {
            uint32_t b[2];
            ldB(b, sW + (q * 32 + j * 8 + r4) * W68 + kb);
            mma_tf32(acc[0][j], a[0], b);
            mma_tf32(acc[1][j], a[1], b);
        }
    }

    #pragma unroll
    for (int s = 0; s < 2; s++) {
        #pragma unroll
        for (int rh = 0; rh < 2; rh++) {
            int gn = base + p * 32 + s * 16 + rh * 8 + r4;
            if (gn < NN) {
                #pragma unroll
                for (int j = 0; j < 4; j++) {
                    int c0 = q * 32 + j * 8 + c2;
                    float ox = acc[s][j][rh * 2]     + __ldg(b1a + c0);
                    float oy = acc[s][j][rh * 2 + 1] + __ldg(b1a + c0 + 1);
                    *(uint32_t*)(g_P + (size_t)gn * 128 + c0) = f2h2(ox, oy);
                }
            }
        }
    }
}

// ============================ EDGE KERNEL (fp16, 512 thr) ====================
// 64-edge tiles, 512 threads (16 warps), 2 CTA/SM = 32 warps/SM.
// Warp layout: p = w&3 (16-row strip), q = w>>2 (col group).
// Total LDS traffic identical to 8-warp layout (GEMM1 B in regs; q-groups disjoint).
#define EO_COL 0                      // int [2][64]
#define EO_ROW 512                    // int [2][64]
#define EO_B1B 1024                   // 64 f
#define EO_XH  1280                   // 64 x 272 (fp16)
#define EO_WB  (EO_XH + 64 * HB)      // 64 x 272 (fp16 W1b)
#define EO_P   (EO_WB + 64 * HB)      // 64 x 272 (fp16 P)
#define SMEM_EDGE (EO_P + 64 * HB)    // 53504 B -> 2 CTAs/SM

__global__ __launch_bounds__(512, 2)
void edge_kernel(const int* __restrict__ eidx, const float* __restrict__ eattr,
                 const float* __restrict__ W1a, const float* __restrict__ W1b,
                 const float* __restrict__ b1b)
{
    extern __shared__ char sm[];
    int*   sCol = (int*)(sm + EO_COL);
    int*   sRow = (int*)(sm + EO_ROW);
    float* sb1b = (float*)(sm + EO_B1B);
    char* sXH = sm + EO_XH;
    char* sWb = sm + EO_WB;
    char* sP  = sm + EO_P;

    const int tid = threadIdx.x, lane = tid & 31, w = tid >> 5;
    const int p = w & 3, q = w >> 2;          // p: 16-row strip (4), q: col group (4)
    const int r4 = lane >> 2, t3 = lane & 3;
    const int cb = t3 * 4, c2 = t3 * 2;
    const int m0 = p * 16;

    // stage W1b (fp16) into smem
    for (int idx = tid; idx < 64 * 64; idx += 512) {
        int r = idx >> 6, kp2 = idx & 63;
        float2 v = *(const float2*)(W1b + r * 128 + kp2 * 2);
        *(uint32_t*)(sWb + r * HB + kp2 * 4) = f2h2(v.x, v.y);
    }
    if (tid < 64) sb1b[tid] = b1b[tid];

    // W1aR (cols 64..127) fp16 fragments -> registers (32 regs/thread)
    uint32_t bfrag[4][4][2];
    #pragma unroll
    for (int k0 = 0; k0 < 4; k0++) {
        #pragma unroll
        for (int j = 0; j < 4; j++) {
            int n0 = q * 32 + j * 8 + r4;
            const float* wp = W1a + n0 * 128 + 64 + k0 * 16 + t3 * 2;
            bfrag[k0][j][0] = f2h2(__ldg(wp),     __ldg(wp + 1));
            bfrag[k0][j][1] = f2h2(__ldg(wp + 8), __ldg(wp + 9));
        }
    }

    const int* rowI = eidx;        // int32 (jax x64 disabled)
    const int* colI = eidx + NE;
    const int step = gridDim.x;
    const int ntiles = NE / 64;

    int t = blockIdx.x;
    if (tid < 64 && t < ntiles) {
        sRow[tid] = rowI[t * 64 + tid];
        sCol[tid] = colI[t * 64 + tid];
    }
    __syncthreads();

    int buf = 0;
    for (; t < ntiles; t += step) {
        const int base = t * 64;
        const int* curCol = sCol + buf * 64;
        const int* curRow = sRow + buf * 64;

        // ---- cp.async: P[col[e]] rows (fp16, 256B/row), overlaps GEMM1 ----
        #pragma unroll
        for (int i = 0; i < 2; i++) {
            int idx = i * 512 + tid;            // 1024 x 16B
            int e = idx >> 4, o16 = (idx & 15) * 16;
            cp_async16(sP + e * HB + o16,
                       (const char*)(g_P + (size_t)curCol[e] * 128) + o16);
        }
        CP_COMMIT();

        // ---- stage eattr tile as fp16 ----
        #pragma unroll
        for (int i = 0; i < 4; i++) {
            int idx = i * 512 + tid;
            int e = idx >> 5, kp2 = idx & 31;
            float2 v = *(const float2*)(eattr + (size_t)(base + e) * 64 + kp2 * 2);
            *(uint32_t*)(sXH + e * HB + kp2 * 4) = f2h2(v.x, v.y);
        }

        // prefetch next tile's indices (overlaps GEMM1)
        int nr = 0, nc = 0;
        int tn = t + step;
        if (tid < 64 && tn < ntiles) {
            nr = rowI[tn * 64 + tid];
            nc = colI[tn * 64 + tid];
        }
        __syncthreads();            // sXH ready

        // ---- GEMM1: eattr @ W1aR^T (K=64 -> 4 k16 steps; B in regs) ----
        float acc[4][4];
        #pragma unroll
        for (int j = 0; j < 4; j++)
            { acc[j][0]=0.f; acc[j][1]=0.f; acc[j][2]=0.f; acc[j][3]=0.f; }

        #pragma unroll
        for (int k0 = 0; k0 < 4; k0++) {
            int kb = k0 * 32 + cb;
            uint32_t a[4];
            ldA_s(a, sXH + (m0 + r4) * HB + kb, HB);
            #pragma unroll
            for (int j = 0; j < 4; j++)
                mma_f16(acc[j], a, bfrag[k0][j]);
        }
        CP_WAIT0();                 // P landed (overlapped with GEMM1)
        __syncthreads();            // sXH free + sP visible

        // ---- epi1: h = fp16(relu(acc + sP)) -> sXH ----
        {
            int r0 = m0 + r4;
            #pragma unroll
            for (int j = 0; j < 4; j++) {
                int c0 = q * 32 + j * 8 + c2;
                float2 pa = h22f2(*(const uint32_t*)(sP + r0 * HB + c0 * 2));
                float2 pb = h22f2(*(const uint32_t*)(sP + (r0 + 8) * HB + c0 * 2));
                *(uint32_t*)(sXH + r0 * HB + c0 * 2) =
                    f2h2(fmaxf(acc[j][0] + pa.x, 0.f), fmaxf(acc[j][1] + pa.y, 0.f));
                *(uint32_t*)(sXH + (r0 + 8) * HB + c0 * 2) =
                    f2h2(fmaxf(acc[j][2] + pb.x, 0.f), fmaxf(acc[j][3] + pb.y, 0.f));
            }
        }
        __syncthreads();

        // ---- GEMM2: h @ W1b^T (K=128 -> 8 k16 steps, N=64) ----
        float acc2[2][4];
        #pragma unroll
        for (int j = 0; j < 2; j++)
            { acc2[j][0]=0.f; acc2[j][1]=0.f; acc2[j][2]=0.f; acc2[j][3]=0.f; }

        #pragma unroll
        for (int k0 = 0; k0 < 8; k0++) {
            int kb = k0 * 32 + cb;
            uint32_t a[4];
            ldA_s(a, sXH + (m0 + r4) * HB + kb, HB);
            #pragma unroll
            for (int j = 0; j < 2; j++) {
                uint32_t b[2];
                ldB(b, sWb + (q * 16 + j * 8 + r4) * HB + kb);
                mma_f16(acc2[j], a, b);
            }
        }

        // ---- epi2: +b1b, scatter-add, count (fire-and-forget) ----
        #pragma unroll
        for (int rh = 0; rh < 2; rh++) {
            int e = m0 + rh * 8 + r4;
            int r = curRow[e];
            if (q == 0 && t3 == 0) atomicAdd(&g_cnt[r], 1.0f);
            float* dst = g_sums + (size_t)r * 64;
            #pragma unroll
            for (int j = 0; j < 2; j++) {
                int c0 = q * 16 + j * 8 + c2;
                REDV2(dst + c0,
                      acc2[j][rh * 2]     + sb1b[c0],
                      acc2[j][rh * 2 + 1] + sb1b[c0 + 1]);
            }
        }

        if (tid < 64) {
            sRow[(buf ^ 1) * 64 + tid] = nr;
            sCol[(buf ^ 1) * 64 + tid] = nc;
        }
        buf ^= 1;
        __syncthreads();
    }
}

// ============================== NODE KERNEL (fp16, proven R14) ===============
#define NO_A   1536                       // 128 x 272 fp16  [src|agg]
#define NO_H   (NO_A + 128 * HB)          // 128 x 272 fp16
#define NO_WA  (NO_H + 128 * HB)          // 128 x 272 fp16
#define NO_WB  (NO_WA + 128 * HB)         // 64 x 272 fp16
#define NO_WR  (NO_WB + 64 * HB)          // 64 x 272 fp16
#define SMEM_NODE (NO_WR + 64 * HB)       // 140800 B

__device__ __forceinline__ void stage_w_h(const float* __restrict__ W, char* dst, int R,
                                          int swap, int nthr) {
    for (int idx = threadIdx.x; idx < R * 64; idx += nthr) {
        int r = idx >> 6, kp2 = idx & 63;
        float2 v = *(const float2*)(W + r * 128 + kp2 * 2);
        int kd = swap ? (kp2 ^ 32) : kp2;
        *(uint32_t*)(dst + r * HB + kd * 4) = f2h2(v.x, v.y);
    }
}

__global__ __launch_bounds__(1024, 1)
void node_kernel(const float* __restrict__ src,
                 const float* __restrict__ W2a, const float* __restrict__ b2a,
                 const float* __restrict__ W2b, const float* __restrict__ b2b,
                 const float* __restrict__ Wr,  const float* __restrict__ br,
                 float* __restrict__ out)
{
    extern __shared__ char sm[];
    float* sb2a = (float*)sm;
    float* sb2b = (float*)(sm + 512);
    float* sbr  = (float*)(sm + 768);
    float* sInv = (float*)(sm + 1024);     // 128 f
    char* sA  = sm + NO_A;
    char* sH  = sm + NO_H;
    char* sWa = sm + NO_WA;
    char* sWb = sm + NO_WB;
    char* sWr = sm + NO_WR;

    const int tid = threadIdx.x, lane = tid & 31, w = tid >> 5;
    stage_w_h(W2a, sWa, 128, 0, 1024);
    stage_w_h(W2b, sWb, 64, 0, 1024);
    stage_w_h(Wr,  sWr, 64, 1, 1024);   // k-halves swapped: A=[src|z] vs concat(z,src)
    if (tid < 128) sb2a[tid] = b2a[tid];
    if (tid < 64)  sb2b[tid] = b2b[tid];
    if (tid < 64)  sbr[tid]  = br[tid];

    const int p = w & 7, jj = w >> 3;   // p: 16-row strip (8), jj: col group (4)
    const int r4 = lane >> 2, t3 = lane & 3;
    const int cb = t3 * 4, c2 = t3 * 2;
    const int m0 = p * 16;

    const int ntiles = (NN + 127) / 128;   // 391
    for (int t = blockIdx.x; t < ntiles; t += gridDim.x) {
        const int base = t * 128;
        __syncthreads();
        if (tid < 128) {
            int gn = base + tid;
            float c = (gn < NN) ? g_cnt[gn] : 1.0f;
            sInv[tid] = 1.0f / fmaxf(c, 1.0f);
        }
        __syncthreads();

        #pragma unroll
        for (int i = 0; i < 4; i++) {
            int idx = i * 1024 + tid;
            int n = idx >> 5, kp2 = idx & 31;
            int gn = base + n;
            float2 vs = make_float2(0.f, 0.f), va = make_float2(0.f, 0.f);
            if (gn < NN) {
                vs = *(const float2*)(src + (size_t)gn * 64 + kp2 * 2);
                float2 s2 = *(const float2*)(g_sums + (size_t)gn * 64 + kp2 * 2);
                float iv = sInv[n];
                va = make_float2(s2.x * iv, s2.y * iv);
            }
            *(uint32_t*)(sA + n * HB + kp2 * 4)        = f2h2(vs.x, vs.y);
            *(uint32_t*)(sA + n * HB + (32 + kp2) * 4) = f2h2(va.x, va.y);
        }
        __syncthreads();

        float acc[4][4];
        #pragma unroll
        for (int j = 0; j < 4; j++) { acc[j][0]=0.f; acc[j][1]=0.f; acc[j][2]=0.f; acc[j][3]=0.f; }
        #pragma unroll
        for (int k0 = 0; k0 < 8; k0++) {
            int kb = k0 * 32 + cb;
            uint32_t a[4];
            ldA_s(a, sA + (m0 + r4) * HB + kb, HB);
            #pragma unroll
            for (int j = 0; j < 4; j++) {
                uint32_t b[2];
                ldB(b, sWa + (jj * 32 + j * 8 + r4) * HB + kb);
                mma_f16(acc[j], a, b);
            }
        }
        #pragma unroll
        for (int j = 0; j < 4; j++) {
            int c0 = jj * 32 + j * 8 + c2;
            float bx = sb2a[c0], by = sb2a[c0 + 1];
            *(uint32_t*)(sH + (m0 + r4) * HB + c0 * 2) =
                f2h2(fmaxf(acc[j][0] + bx, 0.f), fmaxf(acc[j][1] + by, 0.f));
            *(uint32_t*)(sH + (m0 + 8 + r4) * HB + c0 * 2) =
                f2h2(fmaxf(acc[j][2] + bx, 0.f), fmaxf(acc[j][3] + by, 0.f));
        }
        __syncthreads();

        float acc2[2][4];
        #pragma unroll
        for (int j = 0; j < 2; j++) { acc2[j][0]=0.f; acc2[j][1]=0.f; acc2[j][2]=0.f; acc2[j][3]=0.f; }
        #pragma unroll
        for (int k0 = 0; k0 < 8; k0++) {
            int kb = k0 * 32 + cb;
            uint32_t a[4];
            ldA_s(a, sH + (m0 + r4) * HB + kb, HB);
            #pragma unroll
            for (int j = 0; j < 2; j++) {
                uint32_t b[2];
                ldB(b, sWb + (jj * 16 + j * 8 + r4) * HB + kb);
                mma_f16(acc2[j], a, b);
            }
        }
        #pragma unroll
        for (int j = 0; j < 2; j++) {
            int c0 = jj * 16 + j * 8 + c2;
            float bx = sb2b[c0], by = sb2b[c0 + 1];
            *(uint32_t*)(sA + (m0 + r4) * HB + (64 + c0) * 2) =
                f2h2(acc2[j][0] + bx, acc2[j][1] + by);
            *(uint32_t*)(sA + (m0 + 8 + r4) * HB + (64 + c0) * 2) =
                f2h2(acc2[j][2] + bx, acc2[j][3] + by);
        }
        __syncthreads();

        float acc3[2][4];
        #pragma unroll
        for (int j = 0; j < 2; j++) { acc3[j][0]=0.f; acc3[j][1]=0.f; acc3[j][2]=0.f; acc3[j][3]=0.f; }
        #pragma unroll
        for (int k0 = 0; k0 < 8; k0++) {
            int kb = k0 * 32 + cb;
            uint32_t a[4];
            ldA_s(a, sA + (m0 + r4) * HB + kb, HB);
            #pragma unroll
            for (int j = 0; j < 2; j++) {
                uint32_t b[2];
                ldB(b, sWr + (jj * 16 + j * 8 + r4) * HB + kb);
                mma_f16(acc3[j], a, b);
            }
        }
        #pragma unroll
        for (int rh = 0; rh < 2; rh++) {
            int gn = base + m0 + rh * 8 + r4;
            if (gn < NN) {
                #pragma unroll
                for (int j = 0; j < 2; j++) {
                    int c0 = jj * 16 + j * 8 + c2;
                    float2 o = make_float2(acc3[j][rh * 2] + sbr[c0],
                                           acc3[j][rh * 2 + 1] + sbr[c0 + 1]);
                    *(float2*)(out + (size_t)gn * 64 + c0) = o;
                }
            }
        }
    }
}

// ---------------------------------------------------------------------------
extern "C" void kernel_launch(void* const* d_in, const int* in_sizes, int n_in,
                              void* d_out, int out_size) {
    const float* src   = (const float*)d_in[0];
    const int*   eidx  = (const int*)d_in[1];
    const float* eattr = (const float*)d_in[2];
    const float* W1a = (const float*)d_in[5];
    const float* b1a = (const float*)d_in[6];
    const float* W1b = (const float*)d_in[7];
    const float* b1b = (const float*)d_in[8];
    const float* W2a = (const float*)d_in[9];
    const float* b2a = (const float*)d_in[10];
    const float* W2b = (const float*)d_in[11];
    const float* b2b = (const float*)d_in[12];
    const float* Wr  = (const float*)d_in[13];
    const float* br  = (const float*)d_in[14];
    float* out = (float*)d_out;

    cudaFuncSetAttribute(p_kernel,    cudaFuncAttributeMaxDynamicSharedMemorySize, SMEM_P);
    cudaFuncSetAttribute(edge_kernel, cudaFuncAttributeMaxDynamicSharedMemorySize, SMEM_EDGE);
    cudaFuncSetAttribute(node_kernel, cudaFuncAttributeMaxDynamicSharedMemorySize, SMEM_NODE);

    zero_kernel<<<(NN * 16 + 255) / 256, 256>>>();
    p_kernel<<<(NN + 63) / 64, 256, SMEM_P>>>(src, W1a, b1a);
    edge_kernel<<<296, 512, SMEM_EDGE>>>(eidx, eattr, W1a, W1b, b1b);
    node_kernel<<<148, 1024, SMEM_NODE>>>(src, W2a, b2a, W2b, b2b, Wr, br, out);
}

// round 16
// speedup vs baseline: 1.0504x; 1.0504x over previous
#include <cuda_runtime.h>
#include <cuda_fp16.h>
#include <cstdint>

#define NN 50000
#define NE 800000

__device__ __align__(16) float g_sums[NN * 64];
__device__ __align__(16) float g_cnt[NN];
__device__ __align__(16) __half g_P[NN * 128];   // P = src @ W1aL^T + b1a (fp16)

__global__ void zero_kernel() {
    int i = blockIdx.x * blockDim.x + threadIdx.x;
    float4 z = make_float4(0.f, 0.f, 0.f, 0.f);
    if (i < NN * 16) ((float4*)g_sums)[i] = z;
    if (i < NN / 4 + 1 && i * 4 + 3 < NN) ((float4*)g_cnt)[i] = z;
    if (i < 4) g_cnt[NN - 1 - i] = 0.f;
}

__device__ __forceinline__ float to_tf32(float x) {
    float y;
    asm("cvt.rna.tf32.f32 %0, %1;" : "=f"(y) : "f"(x));
    return y;
}
__device__ __forceinline__ uint32_t f2h2(float x, float y) {
    __half2 h = __floats2half2_rn(x, y);
    return *reinterpret_cast<uint32_t*>(&h);
}
__device__ __forceinline__ float2 h22f2(uint32_t u) {
    __half2 h = *reinterpret_cast<__half2*>(&u);
    return __half22float2(h);
}

__device__ __forceinline__ void mma_tf32(float d[4], const uint32_t a[4], const uint32_t b[2]) {
    asm volatile(
        "mma.sync.aligned.m16n8k8.row.col.f32.tf32.tf32.f32 "
        "{%0,%1,%2,%3}, {%4,%5,%6,%7}, {%8,%9}, {%0,%1,%2,%3};"
        : "+f"(d[0]), "+f"(d[1]), "+f"(d[2]), "+f"(d[3])
        : "r"(a[0]), "r"(a[1]), "r"(a[2]), "r"(a[3]), "r"(b[0]), "r"(b[1]));
}
__device__ __forceinline__ void mma_f16(float d[4], const uint32_t a[4], const uint32_t b[2]) {
    asm volatile(
        "mma.sync.aligned.m16n8k16.row.col.f32.f16.f16.f32 "
        "{%0,%1,%2,%3}, {%4,%5,%6,%7}, {%8,%9}, {%0,%1,%2,%3};"
        : "+f"(d[0]), "+f"(d[1]), "+f"(d[2]), "+f"(d[3])
        : "r"(a[0]), "r"(a[1]), "r"(a[2]), "r"(a[3]), "r"(b[0]), "r"(b[1]));
}

__device__ __forceinline__ void ldA_s(uint32_t a[4], const char* p, int stride) {
    a[0] = *(const uint32_t*)p;
    a[1] = *(const uint32_t*)(p + 8 * stride);
    a[2] = *(const uint32_t*)(p + 16);
    a[3] = *(const uint32_t*)(p + 8 * stride + 16);
}
__device__ __forceinline__ void ldB(uint32_t b[2], const char* p) {
    b[0] = *(const uint32_t*)p;
    b[1] = *(const uint32_t*)(p + 16);
}

#define REDV2(ptr, x0, x1) \
    asm volatile("red.global.add.v2.f32 [%0], {%1,%2};" :: "l"(ptr), "f"(x0), "f"(x1) : "memory")

__device__ __forceinline__ void cp_async16(void* dst_smem, const void* src_g) {
    uint32_t d;
    asm("{ .reg .u64 t; cvta.to.shared.u64 t, %1; cvt.u32.u64 %0, t; }" : "=r"(d) : "l"(dst_smem));
    asm volatile("cp.async.cg.shared.global [%0], [%1], 16;" :: "r"(d), "l"(src_g) : "memory");
}
#define CP_COMMIT() asm volatile("cp.async.commit_group;" ::: "memory")
#define CP_WAIT0()  asm volatile("cp.async.wait_group 0;" ::: "memory")

#define W68  272     // tf32 rows: 68 floats
#define HB   272     // fp16 rows: 136 halves (conflict-free, proven)

// ============================ P kernel (tf32 compute, fp16 out) ==============
#define PO_A 0
#define PO_W 17408
#define SMEM_P (PO_W + 34816)

__global__ __launch_bounds__(256, 2)
void p_kernel(const float* __restrict__ src, const float* __restrict__ W1a,
              const float* __restrict__ b1a)
{
    extern __shared__ char sm[];
    char* sA = sm + PO_A;
    char* sW = sm + PO_W;
    const int tid = threadIdx.x, lane = tid & 31, w = tid >> 5;
    const int p = w & 1, q = w >> 1;
    const int r4 = lane >> 2, cb = (lane & 3) * 4, c2 = (lane & 3) * 2;

    for (int idx = tid; idx < 128 * 32; idx += 256) {
        int r = idx >> 5, kp2 = idx & 31;
        float2 v = *(const float2*)(W1a + r * 128 + kp2 * 2);
        v.x = to_tf32(v.x); v.y = to_tf32(v.y);
        *(float2*)(sW + r * W68 + kp2 * 8) = v;
    }

    const int base = blockIdx.x * 64;
    for (int idx = tid; idx < 64 * 32; idx += 256) {
        int n = idx >> 5, kp2 = idx & 31;
        int gn = base + n;
        float2 v = make_float2(0.f, 0.f);
        if (gn < NN) v = *(const float2*)(src + (size_t)gn * 64 + kp2 * 2);
        v.x = to_tf32(v.x); v.y = to_tf32(v.y);
        *(float2*)(sA + n * W68 + kp2 * 8) = v;
    }
    __syncthreads();

    float acc[2][4][4];
    #pragma unroll
    for (int s = 0; s < 2; s++)
        #pragma unroll
        for (int j = 0; j < 4; j++)
            { acc[s][j][0]=0.f; acc[s][j][1]=0.f; acc[s][j][2]=0.f; acc[s][j][3]=0.f; }

    #pragma unroll
    for (int k0 = 0; k0 < 8; k0++) {
        int kb = k0 * 32 + cb;
        uint32_t a[2][4];
        ldA_s(a[0], sA + (p * 32 + r4) * W68 + kb, W68);
        ldA_s(a[1], sA + (p * 32 + 16 + r4) * W68 + kb, W68);
        #pragma unroll
        for (int j = 0; j < 4; j++) {
            uint32_t b[2];
            ldB(b, sW + (q * 32 + j * 8 + r4) * W68 + kb);
            mma_tf32(acc[0][j], a[0], b);
            mma_tf32(acc[1][j], a[1], b);
        }
    }

    #pragma unroll
    for (int s = 0; s < 2; s++) {
        #pragma unroll
        for (int rh = 0; rh < 2; rh++) {
            int gn = base + p * 32 + s * 16 + rh * 8 + r4;
            if (gn < NN) {
                #pragma unroll
                for (int j = 0; j < 4; j++) {
                    int c0 = q * 32 + j * 8 + c2;
                    float ox = acc[s][j][rh * 2]     + __ldg(b1a + c0);
                    float oy = acc[s][j][rh * 2 + 1] + __ldg(b1a + c0 + 1);
                    *(uint32_t*)(g_P + (size_t)gn * 128 + c0) = f2h2(ox, oy);
                }
            }
        }
    }
}

// ============================ EDGE KERNEL (fp16, 128-edge tiles) =============
// 128-edge tiles, 256 threads (8 warps), 2 CTA/SM.
// Warp layout: p = w&3 (32-row group = 2 m16 strips), q = w>>2 (col group of 64).
// W1aR fp16 fragments in registers (64/thread).
#define EO_COL 0                       // int [2][128]
#define EO_ROW 1024                    // int [2][128]
#define EO_B1B 2048                    // 64 f
#define EO_XH  2304                    // 128 x 272 (fp16)
#define EO_WB  (EO_XH + 128 * HB)      // 64 x 272 (fp16 W1b)
#define EO_P   (EO_WB + 64 * HB)       // 128 x 272 (fp16 P)
#define SMEM_EDGE (EO_P + 128 * HB)    // 89344 B -> 2 CTAs/SM

__global__ __launch_bounds__(256, 2)
void edge_kernel(const int* __restrict__ eidx, const float* __restrict__ eattr,
                 const float* __restrict__ W1a, const float* __restrict__ W1b,
                 const float* __restrict__ b1b)
{
    extern __shared__ char sm[];
    int*   sCol = (int*)(sm + EO_COL);
    int*   sRow = (int*)(sm + EO_ROW);
    float* sb1b = (float*)(sm + EO_B1B);
    char* sXH = sm + EO_XH;
    char* sWb = sm + EO_WB;
    char* sP  = sm + EO_P;

    const int tid = threadIdx.x, lane = tid & 31, w = tid >> 5;
    const int p = w & 3, q = w >> 2;          // p: 32-row group (4), q: col group (2)
    const int r4 = lane >> 2, t3 = lane & 3;
    const int cb = t3 * 4, c2 = t3 * 2;
    const int m0 = p * 32;

    // stage W1b (fp16) into smem
    for (int idx = tid; idx < 64 * 64; idx += 256) {
        int r = idx >> 6, kp2 = idx & 63;
        float2 v = *(const float2*)(W1b + r * 128 + kp2 * 2);
        *(uint32_t*)(sWb + r * HB + kp2 * 4) = f2h2(v.x, v.y);
    }
    if (tid < 64) sb1b[tid] = b1b[tid];

    // W1aR (cols 64..127) fp16 fragments -> registers (q*64 + j*8, j<8)
    uint32_t bfrag[4][8][2];
    #pragma unroll
    for (int k0 = 0; k0 < 4; k0++) {
        #pragma unroll
        for (int j = 0; j < 8; j++) {
            int n0 = q * 64 + j * 8 + r4;
            const float* wp = W1a + n0 * 128 + 64 + k0 * 16 + t3 * 2;
            bfrag[k0][j][0] = f2h2(__ldg(wp),     __ldg(wp + 1));
            bfrag[k0][j][1] = f2h2(__ldg(wp + 8), __ldg(wp + 9));
        }
    }

    const int* rowI = eidx;        // int32 (jax x64 disabled)
    const int* colI = eidx + NE;
    const int step = gridDim.x;
    const int ntiles = NE / 128;   // 6250

    int t = blockIdx.x;
    if (tid < 128 && t < ntiles) {
        sRow[tid] = rowI[t * 128 + tid];
        sCol[tid] = colI[t * 128 + tid];
    }
    __syncthreads();

    int buf = 0;
    for (; t < ntiles; t += step) {
        const int base = t * 128;
        const int* curCol = sCol + buf * 128;
        const int* curRow = sRow + buf * 128;

        // ---- cp.async: P[col[e]] rows (fp16, 256B/row), overlaps GEMM1 ----
        #pragma unroll
        for (int i = 0; i < 8; i++) {
            int idx = i * 256 + tid;            // 2048 x 16B
            int e = idx >> 4, o16 = (idx & 15) * 16;
            cp_async16(sP + e * HB + o16,
                       (const char*)(g_P + (size_t)curCol[e] * 128) + o16);
        }
        CP_COMMIT();

        // ---- stage eattr tile as fp16 (128 x 64) ----
        #pragma unroll
        for (int i = 0; i < 16; i++) {
            int idx = i * 256 + tid;
            int e = idx >> 5, kp2 = idx & 31;
            float2 v = *(const float2*)(eattr + (size_t)(base + e) * 64 + kp2 * 2);
            *(uint32_t*)(sXH + e * HB + kp2 * 4) = f2h2(v.x, v.y);
        }

        // prefetch next tile's indices (overlaps GEMM1)
        int nr = 0, nc = 0;
        int tn = t + step;
        if (tid < 128 && tn < ntiles) {
            nr = rowI[tn * 128 + tid];
            nc = colI[tn * 128 + tid];
        }
        __syncthreads();            // sXH ready

        // ---- GEMM1: eattr @ W1aR^T (K=64 -> 4 k16; 2 strips x 8 n8; B in regs) ----
        float acc[2][8][4];
        #pragma unroll
        for (int s = 0; s < 2; s++)
            #pragma unroll
            for (int j = 0; j < 8; j++)
                { acc[s][j][0]=0.f; acc[s][j][1]=0.f; acc[s][j][2]=0.f; acc[s][j][3]=0.f; }

        #pragma unroll
        for (int k0 = 0; k0 < 4; k0++) {
            int kb = k0 * 32 + cb;
            uint32_t a[2][4];
            ldA_s(a[0], sXH + (m0 + r4) * HB + kb, HB);
            ldA_s(a[1], sXH + (m0 + 16 + r4) * HB + kb, HB);
            #pragma unroll
            for (int j = 0; j < 8; j++) {
                mma_f16(acc[0][j], a[0], bfrag[k0][j]);
                mma_f16(acc[1][j], a[1], bfrag[k0][j]);
            }
        }
        CP_WAIT0();                 // P landed (overlapped with GEMM1)
        __syncthreads();            // sXH free + sP visible

        // ---- epi1: h = fp16(relu(acc + sP)) -> sXH ----
        #pragma unroll
        for (int s = 0; s < 2; s++) {
            int r0 = m0 + s * 16 + r4;
            #pragma unroll
            for (int j = 0; j < 8; j++) {
                int c0 = q * 64 + j * 8 + c2;
                float2 pa = h22f2(*(const uint32_t*)(sP + r0 * HB + c0 * 2));
                float2 pb = h22f2(*(const uint32_t*)(sP + (r0 + 8) * HB + c0 * 2));
                *(uint32_t*)(sXH + r0 * HB + c0 * 2) =
                    f2h2(fmaxf(acc[s][j][0] + pa.x, 0.f), fmaxf(acc[s][j][1] + pa.y, 0.f));
                *(uint32_t*)(sXH + (r0 + 8) * HB + c0 * 2) =
                    f2h2(fmaxf(acc[s][j][2] + pb.x, 0.f), fmaxf(acc[s][j][3] + pb.y, 0.f));
            }
        }
        __syncthreads();

        // ---- GEMM2: h @ W1b^T (K=128 -> 8 k16; 2 strips x 4 n8) ----
        float acc2[2][4][4];
        #pragma unroll
        for (int s = 0; s < 2; s++)
            #pragma unroll
            for (int j = 0; j < 4; j++)
                { acc2[s][j][0]=0.f; acc2[s][j][1]=0.f; acc2[s][j][2]=0.f; acc2[s][j][3]=0.f; }

        #pragma unroll
        for (int k0 = 0; k0 < 8; k0++) {
            int kb = k0 * 32 + cb;
            uint32_t a[2][4];
            ldA_s(a[0], sXH + (m0 + r4) * HB + kb, HB);
            ldA_s(a[1], sXH + (m0 + 16 + r4) * HB + kb, HB);
            #pragma unroll
            for (int j = 0; j < 4; j++) {
                uint32_t b[2];
                ldB(b, sWb + (q * 32 + j * 8 + r4) * HB + kb);
                mma_f16(acc2[0][j], a[0], b);
                mma_f16(acc2[1][j], a[1], b);
            }
        }

        // ---- epi2: +b1b, scatter-add, count (fire-and-forget) ----
        #pragma unroll
        for (int s = 0; s < 2; s++) {
            #pragma unroll
            for (int rh = 0; rh < 2; rh++) {
                int e = m0 + s * 16 + rh * 8 + r4;
                int r = curRow[e];
                if (q == 0 && t3 == 0) atomicAdd(&g_cnt[r], 1.0f);
                float* dst = g_sums + (size_t)r * 64;
                #pragma unroll
                for (int j = 0; j < 4; j++) {
                    int c0 = q * 32 + j * 8 + c2;
                    REDV2(dst + c0,
                          acc2[s][j][rh * 2]     + sb1b[c0],
                          acc2[s][j][rh * 2 + 1] + sb1b[c0 + 1]);
                }
            }
        }

        if (tid < 128) {
            sRow[(buf ^ 1) * 128 + tid] = nr;
            sCol[(buf ^ 1) * 128 + tid] = nc;
        }
        buf ^= 1;
        __syncthreads();
    }
}

// ============================== NODE KERNEL (fp16, proven R14) ===============
#define NO_A   1536                       // 128 x 272 fp16  [src|agg]
#define NO_H   (NO_A + 128 * HB)          // 128 x 272 fp16
#define NO_WA  (NO_H + 128 * HB)          // 128 x 272 fp16
#define NO_WB  (NO_WA + 128 * HB)         // 64 x 272 fp16
#define NO_WR  (NO_WB + 64 * HB)          // 64 x 272 fp16
#define SMEM_NODE (NO_WR + 64 * HB)       // 140800 B

__device__ __forceinline__ void stage_w_h(const float* __restrict__ W, char* dst, int R,
                                          int swap, int nthr) {
    for (int idx = threadIdx.x; idx < R * 64; idx += nthr) {
        int r = idx >> 6, kp2 = idx & 63;
        float2 v = *(const float2*)(W + r * 128 + kp2 * 2);
        int kd = swap ? (kp2 ^ 32) : kp2;
        *(uint32_t*)(dst + r * HB + kd * 4) = f2h2(v.x, v.y);
    }
}

__global__ __launch_bounds__(1024, 1)
void node_kernel(const float* __restrict__ src,
                 const float* __restrict__ W2a, const float* __restrict__ b2a,
                 const float* __restrict__ W2b, const float* __restrict__ b2b,
                 const float* __restrict__ Wr,  const float* __restrict__ br,
                 float* __restrict__ out)
{
    extern __shared__ char sm[];
    float* sb2a = (float*)sm;
    float* sb2b = (float*)(sm + 512);
    float* sbr  = (float*)(sm + 768);
    float* sInv = (float*)(sm + 1024);     // 128 f
    char* sA  = sm + NO_A;
    char* sH  = sm + NO_H;
    char* sWa = sm + NO_WA;
    char* sWb = sm + NO_WB;
    char* sWr = sm + NO_WR;

    const int tid = threadIdx.x, lane = tid & 31, w = tid >> 5;
    stage_w_h(W2a, sWa, 128, 0, 1024);
    stage_w_h(W2b, sWb, 64, 0, 1024);
    stage_w_h(Wr,  sWr, 64, 1, 1024);   // k-halves swapped: A=[src|z] vs concat(z,src)
    if (tid < 128) sb2a[tid] = b2a[tid];
    if (tid < 64)  sb2b[tid] = b2b[tid];
    if (tid < 64)  sbr[tid]  = br[tid];

    const int p = w & 7, jj = w >> 3;   // p: 16-row strip (8), jj: col group (4)
    const int r4 = lane >> 2, t3 = lane & 3;
    const int cb = t3 * 4, c2 = t3 * 2;
    const int m0 = p * 16;

    const int ntiles = (NN + 127) / 128;   // 391
    for (int t = blockIdx.x; t < ntiles; t += gridDim.x) {
        const int base = t * 128;
        __syncthreads();
        if (tid < 128) {
            int gn = base + tid;
            float c = (gn < NN) ? g_cnt[gn] : 1.0f;
            sInv[tid] = 1.0f / fmaxf(c, 1.0f);
        }
        __syncthreads();

        #pragma unroll
        for (int i = 0; i < 4; i++) {
            int idx = i * 1024 + tid;
            int n = idx >> 5, kp2 = idx & 31;
            int gn = base + n;
            float2 vs = make_float2(0.f, 0.f), va = make_float2(0.f, 0.f);
            if (gn < NN) {
                vs = *(const float2*)(src + (size_t)gn * 64 + kp2 * 2);
                float2 s2 = *(const float2*)(g_sums + (size_t)gn * 64 + kp2 * 2);
                float iv = sInv[n];
                va = make_float2(s2.x * iv, s2.y * iv);
            }
            *(uint32_t*)(sA + n * HB + kp2 * 4)        = f2h2(vs.x, vs.y);
            *(uint32_t*)(sA + n * HB + (32 + kp2) * 4) = f2h2(va.x, va.y);
        }
        __syncthreads();

        float acc[4][4];
        #pragma unroll
        for (int j = 0; j < 4; j++) { acc[j][0]=0.f; acc[j][1]=0.f; acc[j][2]=0.f; acc[j][3]=0.f; }
        #pragma unroll
        for (int k0 = 0; k0 < 8; k0++) {
            int kb = k0 * 32 + cb;
            uint32_t a[4];
            ldA_s(a, sA + (m0 + r4) * HB + kb, HB);
            #pragma unroll
            for (int j = 0; j < 4; j++) {
                uint32_t b[2];
                ldB(b, sWa + (jj * 32 + j * 8 + r4) * HB + kb);
                mma_f16(acc[j], a, b);
            }
        }
        #pragma unroll
        for (int j = 0; j < 4; j++) {
            int c0 = jj * 32 + j * 8 + c2;
            float bx = sb2a[c0], by = sb2a[c0 + 1];
            *(uint32_t*)(sH + (m0 + r4) * HB + c0 * 2) =
                f2h2(fmaxf(acc[j][0] + bx, 0.f), fmaxf(acc[j][1] + by, 0.f));
            *(uint32_t*)(sH + (m0 + 8 + r4) * HB + c0 * 2) =
                f2h2(fmaxf(acc[j][2] + bx, 0.f), fmaxf(acc[j][3] + by, 0.f));
        }
        __syncthreads();

        float acc2[2][4];
        #pragma unroll
        for (int j = 0; j < 2; j++) { acc2[j][0]=0.f; acc2[j][1]=0.f; acc2[j][2]=0.f; acc2[j][3]=0.f; }
        #pragma unroll
        for (int k0 = 0; k0 < 8; k0++) {
            int kb = k0 * 32 + cb;
            uint32_t a[4];
            ldA_s(a, sH + (m0 + r4) * HB + kb, HB);
            #pragma unroll
            for (int j = 0; j < 2; j++) {
                uint32_t b[2];
                ldB(b, sWb + (jj * 16 + j * 8 + r4) * HB + kb);
                mma_f16(acc2[j], a, b);
            }
        }
        #pragma unroll
        for (int j = 0; j < 2; j++) {
            int c0 = jj * 16 + j * 8 + c2;
            float bx = sb2b[c0], by = sb2b[c0 + 1];
            *(uint32_t*)(sA + (m0 + r4) * HB + (64 + c0) * 2) =
                f2h2(acc2[j][0] + bx, acc2[j][1] + by);
            *(uint32_t*)(sA + (m0 + 8 + r4) * HB + (64 + c0) * 2) =
                f2h2(acc2[j][2] + bx, acc2[j][3] + by);
        }
        __syncthreads();

        float acc3[2][4];
        #pragma unroll
        for (int j = 0; j < 2; j++) { acc3[j][0]=0.f; acc3[j][1]=0.f; acc3[j][2]=0.f; acc3[j][3]=0.f; }
        #pragma unroll
        for (int k0 = 0; k0 < 8; k0++) {
            int kb = k0 * 32 + cb;
            uint32_t a[4];
            ldA_s(a, sA + (m0 + r4) * HB + kb, HB);
            #pragma unroll
            for (int j = 0; j < 2; j++) {
                uint32_t b[2];
                ldB(b, sWr + (jj * 16 + j * 8 + r4) * HB + kb);
                mma_f16(acc3[j], a, b);
            }
        }
        #pragma unroll
        for (int rh = 0; rh < 2; rh++) {
            int gn = base + m0 + rh * 8 + r4;
            if (gn < NN) {
                #pragma unroll
                for (int j = 0; j < 2; j++) {
                    int c0 = jj * 16 + j * 8 + c2;
                    float2 o = make_float2(acc3[j][rh * 2] + sbr[c0],
                                           acc3[j][rh * 2 + 1] + sbr[c0 + 1]);
                    *(float2*)(out + (size_t)gn * 64 + c0) = o;
                }
            }
        }
    }
}

// ---------------------------------------------------------------------------
extern "C" void kernel_launch(void* const* d_in, const int* in_sizes, int n_in,
                              void* d_out, int out_size) {
    const float* src   = (const float*)d_in[0];
    const int*   eidx  = (const int*)d_in[1];
    const float* eattr = (const float*)d_in[2];
    const float* W1a = (const float*)d_in[5];
    const float* b1a = (const float*)d_in[6];
    const float* W1b = (const float*)d_in[7];
    const float* b1b = (const float*)d_in[8];
    const float* W2a = (const float*)d_in[9];
    const float* b2a = (const float*)d_in[10];
    const float* W2b = (const float*)d_in[11];
    const float* b2b = (const float*)d_in[12];
    const float* Wr  = (const float*)d_in[13];
    const float* br  = (const float*)d_in[14];
    float* out = (float*)d_out;

    cudaFuncSetAttribute(p_kernel,    cudaFuncAttributeMaxDynamicSharedMemorySize, SMEM_P);
    cudaFuncSetAttribute(edge_kernel, cudaFuncAttributeMaxDynamicSharedMemorySize, SMEM_EDGE);
    cudaFuncSetAttribute(node_kernel, cudaFuncAttributeMaxDynamicSharedMemorySize, SMEM_NODE);

    zero_kernel<<<(NN * 16 + 255) / 256, 256>>>();
    p_kernel<<<(NN + 63) / 64, 256, SMEM_P>>>(src, W1a, b1a);
    edge_kernel<<<296, 256, SMEM_EDGE>>>(eidx, eattr, W1a, W1b, b1b);
    node_kernel<<<148, 1024, SMEM_NODE>>>(src, W2a, b2a, W2b, b2b, Wr, br, out);
}

// round 17
// speedup vs baseline: 1.0999x; 1.0471x over previous
#include <cuda_runtime.h>
#include <cuda_fp16.h>
#include <cstdint>

#define NN 50000
#define NE 800000

__device__ __align__(16) float g_sums[NN * 64];
__device__ __align__(16) float g_cnt[NN];
__device__ __align__(16) __half g_P[NN * 128];   // P = src @ W1aL^T + b1a (fp16)

__global__ void zero_kernel() {
    int i = blockIdx.x * blockDim.x + threadIdx.x;
    float4 z = make_float4(0.f, 0.f, 0.f, 0.f);
    if (i < NN * 16) ((float4*)g_sums)[i] = z;
    if (i < NN / 4 + 1 && i * 4 + 3 < NN) ((float4*)g_cnt)[i] = z;
    if (i < 4) g_cnt[NN - 1 - i] = 0.f;
}

__device__ __forceinline__ float to_tf32(float x) {
    float y;
    asm("cvt.rna.tf32.f32 %0, %1;" : "=f"(y) : "f"(x));
    return y;
}
__device__ __forceinline__ uint32_t f2h2(float x, float y) {
    __half2 h = __floats2half2_rn(x, y);
    return *reinterpret_cast<uint32_t*>(&h);
}
__device__ __forceinline__ float2 h22f2(uint32_t u) {
    __half2 h = *reinterpret_cast<__half2*>(&u);
    return __half22float2(h);
}

__device__ __forceinline__ void mma_tf32(float d[4], const uint32_t a[4], const uint32_t b[2]) {
    asm volatile(
        "mma.sync.aligned.m16n8k8.row.col.f32.tf32.tf32.f32 "
        "{%0,%1,%2,%3}, {%4,%5,%6,%7}, {%8,%9}, {%0,%1,%2,%3};"
        : "+f"(d[0]), "+f"(d[1]), "+f"(d[2]), "+f"(d[3])
        : "r"(a[0]), "r"(a[1]), "r"(a[2]), "r"(a[3]), "r"(b[0]), "r"(b[1]));
}
__device__ __forceinline__ void mma_f16(float d[4], const uint32_t a[4], const uint32_t b[2]) {
    asm volatile(
        "mma.sync.aligned.m16n8k16.row.col.f32.f16.f16.f32 "
        "{%0,%1,%2,%3}, {%4,%5,%6,%7}, {%8,%9}, {%0,%1,%2,%3};"
        : "+f"(d[0]), "+f"(d[1]), "+f"(d[2]), "+f"(d[3])
        : "r"(a[0]), "r"(a[1]), "r"(a[2]), "r"(a[3]), "r"(b[0]), "r"(b[1]));
}

__device__ __forceinline__ void ldA_s(uint32_t a[4], const char* p, int stride) {
    a[0] = *(const uint32_t*)p;
    a[1] = *(const uint32_t*)(p + 8 * stride);
    a[2] = *(const uint32_t*)(p + 16);
    a[3] = *(const uint32_t*)(p + 8 * stride + 16);
}
__device__ __forceinline__ void ldB(uint32_t b[2], const char* p) {
    b[0] = *(const uint32_t*)p;
    b[1] = *(const uint32_t*)(p + 16);
}

#define REDV4(ptr, x0, x1, x2, x3) \
    asm volatile("red.global.add.v4.f32 [%0], {%1,%2,%3,%4};" \
        :: "l"(ptr), "f"(x0), "f"(x1), "f"(x2), "f"(x3) : "memory")

__device__ __forceinline__ void cp_async16(void* dst_smem, const void* src_g) {
    uint32_t d;
    asm("{ .reg .u64 t; cvta.to.shared.u64 t, %1; cvt.u32.u64 %0, t; }" : "=r"(d) : "l"(dst_smem));
    asm volatile("cp.async.cg.shared.global [%0], [%1], 16;" :: "r"(d), "l"(src_g) : "memory");
}
#define CP_COMMIT() asm volatile("cp.async.commit_group;" ::: "memory")
#define CP_WAIT0()  asm volatile("cp.async.wait_group 0;" ::: "memory")

#define W68  272     // tf32 rows: 68 floats
#define HB   272     // fp16 rows: 136 halves (conflict-free, proven)

// ============================ P kernel (tf32 compute, fp16 out) ==============
#define PO_A 0
#define PO_W 17408
#define SMEM_P (PO_W + 34816)

__global__ __launch_bounds__(256, 2)
void p_kernel(const float* __restrict__ src, const float* __restrict__ W1a,
              const float* __restrict__ b1a)
{
    extern __shared__ char sm[];
    char* sA = sm + PO_A;
    char* sW = sm + PO_W;
    const int tid = threadIdx.x, lane = tid & 31, w = tid >> 5;
    const int p = w & 1, q = w >> 1;
    const int r4 = lane >> 2, cb = (lane & 3) * 4, c2 = (lane & 3) * 2;

    for (int idx = tid; idx < 128 * 32; idx += 256) {
        int r = idx >> 5, kp2 = idx & 31;
        float2 v = *(const float2*)(W1a + r * 128 + kp2 * 2);
        v.x = to_tf32(v.x); v.y = to_tf32(v.y);
        *(float2*)(sW + r * W68 + kp2 * 8) = v;
    }

    const int base = blockIdx.x * 64;
    for (int idx = tid; idx < 64 * 32; idx += 256) {
        int n = idx >> 5, kp2 = idx & 31;
        int gn = base + n;
        float2 v = make_float2(0.f, 0.f);
        if (gn < NN) v = *(const float2*)(src + (size_t)gn * 64 + kp2 * 2);
        v.x = to_tf32(v.x); v.y = to_tf32(v.y);
        *(float2*)(sA + n * W68 + kp2 * 8) = v;
    }
    __syncthreads();

    float acc[2][4][4];
    #pragma unroll
    for (int s = 0; s < 2; s++)
        #pragma unroll
        for (int j = 0; j < 4; j++)
            { acc[s][j][0]=0.f; acc[s][j][1]=0.f; acc[s][j][2]=0.f; acc[s][j][3]=0.f; }

    #pragma unroll
    for (int k0 = 0; k0 < 8; k0++) {
        int kb = k0 * 32 + cb;
        uint32_t a[2][4];
        ldA_s(a[0], sA + (p * 32 + r4) * W68 + kb, W68);
        ldA_s(a[1], sA + (p * 32 + 16 + r4) * W68 + kb, W68);
        #pragma unroll
        for (int j = 0; j < 4; j++) {
            uint32_t b[2];
            ldB(b, sW + (q * 32 + j * 8 + r4) * W68 + kb);
            mma_tf32(acc[0][j], a[0], b);
            mma_tf32(acc[1][j], a[1], b);
        }
    }

    #pragma unroll
    for (int s = 0; s < 2; s++) {
        #pragma unroll
        for (int rh = 0; rh < 2; rh++) {
            int gn = base + p * 32 + s * 16 + rh * 8 + r4;
            if (gn < NN) {
                #pragma unroll
                for (int j = 0; j < 4; j++) {
                    int c0 = q * 32 + j * 8 + c2;
                    float ox = acc[s][j][rh * 2]     + __ldg(b1a + c0);
                    float oy = acc[s][j][rh * 2 + 1] + __ldg(b1a + c0 + 1);
                    *(uint32_t*)(g_P + (size_t)gn * 128 + c0) = f2h2(ox, oy);
                }
            }
        }
    }
}

// ============================ EDGE KERNEL (fp16, R14 shape) ==================
// 64-edge tiles, 256 threads (8 warps), 2 CTA/SM.
// Scatter: lane-pair shuffle packs 2x REDV2 -> 1x REDV4 (halves LTS lane-ops).
#define EO_COL 0                      // int [2][64]
#define EO_ROW 512                    // int [2][64]
#define EO_B1B 1024                   // 64 f
#define EO_XH  1280                   // 64 x 272 (fp16)
#define EO_WB  (EO_XH + 64 * HB)      // 64 x 272 (fp16 W1b)
#define EO_P   (EO_WB + 64 * HB)      // 64 x 272 (fp16 P)
#define SMEM_EDGE (EO_P + 64 * HB)    // 53504 B -> 2 CTAs/SM

__global__ __launch_bounds__(256, 2)
void edge_kernel(const int* __restrict__ eidx, const float* __restrict__ eattr,
                 const float* __restrict__ W1a, const float* __restrict__ W1b,
                 const float* __restrict__ b1b)
{
    extern __shared__ char sm[];
    int*   sCol = (int*)(sm + EO_COL);
    int*   sRow = (int*)(sm + EO_ROW);
    float* sb1b = (float*)(sm + EO_B1B);
    char* sXH = sm + EO_XH;
    char* sWb = sm + EO_WB;
    char* sP  = sm + EO_P;

    const int tid = threadIdx.x, lane = tid & 31, w = tid >> 5;
    const int p = w & 1, q = w >> 1;
    const int r4 = lane >> 2, t3 = lane & 3;
    const int cb = t3 * 4, c2 = t3 * 2;

    // stage W1b (fp16) into smem
    for (int idx = tid; idx < 64 * 64; idx += 256) {
        int r = idx >> 6, kp2 = idx & 63;
        float2 v = *(const float2*)(W1b + r * 128 + kp2 * 2);
        *(uint32_t*)(sWb + r * HB + kp2 * 4) = f2h2(v.x, v.y);
    }
    if (tid < 64) sb1b[tid] = b1b[tid];

    // W1aR (cols 64..127) fp16 fragments -> registers
    uint32_t bfrag[4][4][2];
    #pragma unroll
    for (int k0 = 0; k0 < 4; k0++) {
        #pragma unroll
        for (int j = 0; j < 4; j++) {
            int n0 = q * 32 + j * 8 + r4;
            const float* wp = W1a + n0 * 128 + 64 + k0 * 16 + t3 * 2;
            bfrag[k0][j][0] = f2h2(__ldg(wp),     __ldg(wp + 1));
            bfrag[k0][j][1] = f2h2(__ldg(wp + 8), __ldg(wp + 9));
        }
    }

    const int* rowI = eidx;        // int32 (jax x64 disabled)
    const int* colI = eidx + NE;
    const int step = gridDim.x;
    const int ntiles = NE / 64;

    int t = blockIdx.x;
    if (tid < 64 && t < ntiles) {
        sRow[tid] = rowI[t * 64 + tid];
        sCol[tid] = colI[t * 64 + tid];
    }
    __syncthreads();

    int buf = 0;
    for (; t < ntiles; t += step) {
        const int base = t * 64;
        const int* curCol = sCol + buf * 64;
        const int* curRow = sRow + buf * 64;

        // ---- cp.async: P[col[e]] rows (fp16, 256B/row), overlaps GEMM1 ----
        #pragma unroll
        for (int i = 0; i < 4; i++) {
            int idx = i * 256 + tid;            // 1024 x 16B
            int e = idx >> 4, o16 = (idx & 15) * 16;
            cp_async16(sP + e * HB + o16,
                       (const char*)(g_P + (size_t)curCol[e] * 128) + o16);
        }
        CP_COMMIT();

        // ---- stage eattr tile as fp16 ----
        #pragma unroll
        for (int i = 0; i < 8; i++) {
            int idx = i * 256 + tid;
            int e = idx >> 5, kp2 = idx & 31;
            float2 v = *(const float2*)(eattr + (size_t)(base + e) * 64 + kp2 * 2);
            *(uint32_t*)(sXH + e * HB + kp2 * 4) = f2h2(v.x, v.y);
        }

        // prefetch next tile's indices (overlaps GEMM1)
        int nr = 0, nc = 0;
        int tn = t + step;
        if (tid < 64 && tn < ntiles) {
            nr = rowI[tn * 64 + tid];
            nc = colI[tn * 64 + tid];
        }
        __syncthreads();            // sXH ready

        // ---- GEMM1: eattr @ W1aR^T (K=64 -> 4 k16 steps; B in regs) ----
        float acc[2][4][4];
        #pragma unroll
        for (int s = 0; s < 2; s++)
            #pragma unroll
            for (int j = 0; j < 4; j++)
                { acc[s][j][0]=0.f; acc[s][j][1]=0.f; acc[s][j][2]=0.f; acc[s][j][3]=0.f; }

        #pragma unroll
        for (int k0 = 0; k0 < 4; k0++) {
            int kb = k0 * 32 + cb;
            uint32_t a[2][4];
            ldA_s(a[0], sXH + (p * 32 + r4) * HB + kb, HB);
            ldA_s(a[1], sXH + (p * 32 + 16 + r4) * HB + kb, HB);
            #pragma unroll
            for (int j = 0; j < 4; j++) {
                mma_f16(acc[0][j], a[0], bfrag[k0][j]);
                mma_f16(acc[1][j], a[1], bfrag[k0][j]);
            }
        }
        CP_WAIT0();                 // P landed (overlapped with GEMM1)
        __syncthreads();            // sXH free + sP visible

        // ---- epi1: h = fp16(relu(acc + sP)) -> sXH ----
        #pragma unroll
        for (int s = 0; s < 2; s++) {
            int r0 = p * 32 + s * 16 + r4;
            #pragma unroll
            for (int j = 0; j < 4; j++) {
                int c0 = q * 32 + j * 8 + c2;
                float2 pa = h22f2(*(const uint32_t*)(sP + r0 * HB + c0 * 2));
                float2 pb = h22f2(*(const uint32_t*)(sP + (r0 + 8) * HB + c0 * 2));
                *(uint32_t*)(sXH + r0 * HB + c0 * 2) =
                    f2h2(fmaxf(acc[s][j][0] + pa.x, 0.f), fmaxf(acc[s][j][1] + pa.y, 0.f));
                *(uint32_t*)(sXH + (r0 + 8) * HB + c0 * 2) =
                    f2h2(fmaxf(acc[s][j][2] + pb.x, 0.f), fmaxf(acc[s][j][3] + pb.y, 0.f));
            }
        }
        __syncthreads();

        // ---- GEMM2: h @ W1b^T (K=128 -> 8 k16 steps, N=64) ----
        float acc2[2][2][4];
        #pragma unroll
        for (int s = 0; s < 2; s++)
            #pragma unroll
            for (int j = 0; j < 2; j++)
                { acc2[s][j][0]=0.f; acc2[s][j][1]=0.f; acc2[s][j][2]=0.f; acc2[s][j][3]=0.f; }

        #pragma unroll
        for (int k0 = 0; k0 < 8; k0++) {
            int kb = k0 * 32 + cb;
            uint32_t a[2][4];
            ldA_s(a[0], sXH + (p * 32 + r4) * HB + kb, HB);
            ldA_s(a[1], sXH + (p * 32 + 16 + r4) * HB + kb, HB);
            #pragma unroll
            for (int j = 0; j < 2; j++) {
                uint32_t b[2];
                ldB(b, sWb + (q * 16 + j * 8 + r4) * HB + kb);
                mma_f16(acc2[0][j], a[0], b);
                mma_f16(acc2[1][j], a[1], b);
            }
        }

        // ---- epi2: +b1b, shuffle-packed REDV4 scatter, count ----
        #pragma unroll
        for (int s = 0; s < 2; s++) {
            int eA = p * 32 + s * 16 + r4;     // row for vals 0,1
            int eB = eA + 8;                   // row for vals 2,3
            int rA = curRow[eA], rB = curRow[eB];
            if (q == 0 && t3 == 0) {
                atomicAdd(&g_cnt[rA], 1.0f);
                atomicAdd(&g_cnt[rB], 1.0f);
            }
            #pragma unroll
            for (int j = 0; j < 2; j++) {
                int c0 = q * 16 + j * 8 + c2;       // own 2 cols
                float v0 = acc2[s][j][0] + sb1b[c0];
                float v1 = acc2[s][j][1] + sb1b[c0 + 1];
                float v2 = acc2[s][j][2] + sb1b[c0];
                float v3 = acc2[s][j][3] + sb1b[c0 + 1];
                // pair exchange: odd lane sends rowA pair, even lane sends rowB pair
                float sx = (t3 & 1) ? v0 : v2;
                float sy = (t3 & 1) ? v1 : v3;
                float rx = __shfl_xor_sync(0xffffffff, sx, 1);
                float ry = __shfl_xor_sync(0xffffffff, sy, 1);
                int cb4 = q * 16 + j * 8 + (t3 & 2) * 2;   // 4-col base for this pair
                if ((t3 & 1) == 0) {
                    REDV4(g_sums + (size_t)rA * 64 + cb4, v0, v1, rx, ry);
                } else {
                    REDV4(g_sums + (size_t)rB * 64 + cb4, rx, ry, v2, v3);
                }
            }
        }

        if (tid < 64) {
            sRow[(buf ^ 1) * 64 + tid] = nr;
            sCol[(buf ^ 1) * 64 + tid] = nc;
        }
        buf ^= 1;
        __syncthreads();
    }
}

// ============================== NODE KERNEL (fp16, proven R14) ===============
#define NO_A   1536                       // 128 x 272 fp16  [src|agg]
#define NO_H   (NO_A + 128 * HB)          // 128 x 272 fp16
#define NO_WA  (NO_H + 128 * HB)          // 128 x 272 fp16
#define NO_WB  (NO_WA + 128 * HB)         // 64 x 272 fp16
#define NO_WR  (NO_WB + 64 * HB)          // 64 x 272 fp16
#define SMEM_NODE (NO_WR + 64 * HB)       // 140800 B

__device__ __forceinline__ void stage_w_h(const float* __restrict__ W, char* dst, int R,
                                          int swap, int nthr) {
    for (int idx = threadIdx.x; idx < R * 64; idx += nthr) {
        int r = idx >> 6, kp2 = idx & 63;
        float2 v = *(const float2*)(W + r * 128 + kp2 * 2);
        int kd = swap ? (kp2 ^ 32) : kp2;
        *(uint32_t*)(dst + r * HB + kd * 4) = f2h2(v.x, v.y);
    }
}

__global__ __launch_bounds__(1024, 1)
void node_kernel(const float* __restrict__ src,
                 const float* __restrict__ W2a, const float* __restrict__ b2a,
                 const float* __restrict__ W2b, const float* __restrict__ b2b,
                 const float* __restrict__ Wr,  const float* __restrict__ br,
                 float* __restrict__ out)
{
    extern __shared__ char sm[];
    float* sb2a = (float*)sm;
    float* sb2b = (float*)(sm + 512);
    float* sbr  = (float*)(sm + 768);
    float* sInv = (float*)(sm + 1024);     // 128 f
    char* sA  = sm + NO_A;
    char* sH  = sm + NO_H;
    char* sWa = sm + NO_WA;
    char* sWb = sm + NO_WB;
    char* sWr = sm + NO_WR;

    const int tid = threadIdx.x, lane = tid & 31, w = tid >> 5;
    stage_w_h(W2a, sWa, 128, 0, 1024);
    stage_w_h(W2b, sWb, 64, 0, 1024);
    stage_w_h(Wr,  sWr, 64, 1, 1024);   // k-halves swapped: A=[src|z] vs concat(z,src)
    if (tid < 128) sb2a[tid] = b2a[tid];
    if (tid < 64)  sb2b[tid] = b2b[tid];
    if (tid < 64)  sbr[tid]  = br[tid];

    const int p = w & 7, jj = w >> 3;   // p: 16-row strip (8), jj: col group (4)
    const int r4 = lane >> 2, t3 = lane & 3;
    const int cb = t3 * 4, c2 = t3 * 2;
    const int m0 = p * 16;

    const int ntiles = (NN + 127) / 128;   // 391
    for (int t = blockIdx.x; t < ntiles; t += gridDim.x) {
        const int base = t * 128;
        __syncthreads();
        if (tid < 128) {
            int gn = base + tid;
            float c = (gn < NN) ? g_cnt[gn] : 1.0f;
            sInv[tid] = 1.0f / fmaxf(c, 1.0f);
        }
        __syncthreads();

        #pragma unroll
        for (int i = 0; i < 4; i++) {
            int idx = i * 1024 + tid;
            int n = idx >> 5, kp2 = idx & 31;
            int gn = base + n;
            float2 vs = make_float2(0.f, 0.f), va = make_float2(0.f, 0.f);
            if (gn < NN) {
                vs = *(const float2*)(src + (size_t)gn * 64 + kp2 * 2);
                float2 s2 = *(const float2*)(g_sums + (size_t)gn * 64 + kp2 * 2);
                float iv = sInv[n];
                va = make_float2(s2.x * iv, s2.y * iv);
            }
            *(uint32_t*)(sA + n * HB + kp2 * 4)        = f2h2(vs.x, vs.y);
            *(uint32_t*)(sA + n * HB + (32 + kp2) * 4) = f2h2(va.x, va.y);
        }
        __syncthreads();

        float acc[4][4];
        #pragma unroll
        for (int j = 0; j < 4; j++) { acc[j][0]=0.f; acc[j][1]=0.f; acc[j][2]=0.f; acc[j][3]=0.f; }
        #pragma unroll
        for (int k0 = 0; k0 < 8; k0++) {
            int kb = k0 * 32 + cb;
            uint32_t a[4];
            ldA_s(a, sA + (m0 + r4) * HB + kb, HB);
            #pragma unroll
            for (int j = 0; j < 4; j++) {
                uint32_t b[2];
                ldB(b, sWa + (jj * 32 + j * 8 + r4) * HB + kb);
                mma_f16(acc[j], a, b);
            }
        }
        #pragma unroll
        for (int j = 0; j < 4; j++) {
            int c0 = jj * 32 + j * 8 + c2;
            float bx = sb2a[c0], by = sb2a[c0 + 1];
            *(uint32_t*)(sH + (m0 + r4) * HB + c0 * 2) =
                f2h2(fmaxf(acc[j][0] + bx, 0.f), fmaxf(acc[j][1] + by, 0.f));
            *(uint32_t*)(sH + (m0 + 8 + r4) * HB + c0 * 2) =
                f2h2(fmaxf(acc[j][2] + bx, 0.f), fmaxf(acc[j][3] + by, 0.f));
        }
        __syncthreads();

        float acc2[2][4];
        #pragma unroll
        for (int j = 0; j < 2; j++) { acc2[j][0]=0.f; acc2[j][1]=0.f; acc2[j][2]=0.f; acc2[j][3]=0.f; }
        #pragma unroll
        for (int k0 = 0; k0 < 8; k0++) {
            int kb = k0 * 32 + cb;
            uint32_t a[4];
            ldA_s(a, sH + (m0 + r4) * HB + kb, HB);
            #pragma unroll
            for (int j = 0; j < 2; j++) {
                uint32_t b[2];
                ldB(b, sWb + (jj * 16 + j * 8 + r4) * HB + kb);
                mma_f16(acc2[j], a, b);
            }
        }
        #pragma unroll
        for (int j = 0; j < 2; j++) {
            int c0 = jj * 16 + j * 8 + c2;
            float bx = sb2b[c0], by = sb2b[c0 + 1];
            *(uint32_t*)(sA + (m0 + r4) * HB + (64 + c0) * 2) =
                f2h2(acc2[j][0] + bx, acc2[j][1] + by);
            *(uint32_t*)(sA + (m0 + 8 + r4) * HB + (64 + c0) * 2) =
                f2h2(acc2[j][2] + bx, acc2[j][3] + by);
        }
        __syncthreads();

        float acc3[2][4];
        #pragma unroll
        for (int j = 0; j < 2; j++) { acc3[j][0]=0.f; acc3[j][1]=0.f; acc3[j][2]=0.f; acc3[j][3]=0.f; }
        #pragma unroll
        for (int k0 = 0; k0 < 8; k0++) {
            int kb = k0 * 32 + cb;
            uint32_t a[4];
            ldA_s(a, sA + (m0 + r4) * HB + kb, HB);
            #pragma unroll
            for (int j = 0; j < 2; j++) {
                uint32_t b[2];
                ldB(b, sWr + (jj * 16 + j * 8 + r4) * HB + kb);
                mma_f16(acc3[j], a, b);
            }
        }
        #pragma unroll
        for (int rh = 0; rh < 2; rh++) {
            int gn = base + m0 + rh * 8 + r4;
            if (gn < NN) {
                #pragma unroll
                for (int j = 0; j < 2; j++) {
                    int c0 = jj * 16 + j * 8 + c2;
                    float2 o = make_float2(acc3[j][rh * 2] + sbr[c0],
                                           acc3[j][rh * 2 + 1] + sbr[c0 + 1]);
                    *(float2*)(out + (size_t)gn * 64 + c0) = o;
                }
            }
        }
    }
}

// ---------------------------------------------------------------------------
extern "C" void kernel_launch(void* const* d_in, const int* in_sizes, int n_in,
                              void* d_out, int out_size) {
    const float* src   = (const float*)d_in[0];
    const int*   eidx  = (const int*)d_in[1];
    const float* eattr = (const float*)d_in[2];
    const float* W1a = (const float*)d_in[5];
    const float* b1a = (const float*)d_in[6];
    const float* W1b = (const float*)d_in[7];
    const float* b1b = (const float*)d_in[8];
    const float* W2a = (const float*)d_in[9];
    const float* b2a = (const float*)d_in[10];
    const float* W2b = (const float*)d_in[11];
    const float* b2b = (const float*)d_in[12];
    const float* Wr  = (const float*)d_in[13];
    const float* br  = (const float*)d_in[14];
    float* out = (float*)d_out;

    cudaFuncSetAttribute(p_kernel,    cudaFuncAttributeMaxDynamicSharedMemorySize, SMEM_P);
    cudaFuncSetAttribute(edge_kernel, cudaFuncAttributeMaxDynamicSharedMemorySize, SMEM_EDGE);
    cudaFuncSetAttribute(node_kernel, cudaFuncAttributeMaxDynamicSharedMemorySize, SMEM_NODE);

    zero_kernel<<<(NN * 16 + 255) / 256, 256>>>();
    p_kernel<<<(NN + 63) / 64, 256, SMEM_P>>>(src, W1a, b1a);
    edge_kernel<<<296, 256, SMEM_EDGE>>>(eidx, eattr, W1a, W1b, b1b);
    node_kernel<<<148, 1024, SMEM_NODE>>>(src, W2a, b2a, W2b, b2b, Wr, br, out);
}